// round 4
// baseline (speedup 1.0000x reference)
#include <cuda_runtime.h>
#include <math.h>
#include <stdint.h>

#define LQ      37440
#define LIN     37440
#define DM      256
#define NHEADS  8
#define CHEAD   32

// scratch (allocation-free per harness rules)
__device__ float g_value  [LIN * DM];
__device__ float g_off    [LQ * 384];
__device__ float g_attn   [LQ * 128];
__device__ float g_sampled[LQ * DM];

// ---------------------------------------------------------------------------
// tf32 tensor-core GEMM, double-buffered smem pipeline.
// BM=128, BN=128, BK=16, 256 threads (8 warps 2x4), warp tile 64x32.
// N % 128 == 0, K % 16 == 0. M bounds-checked.
// ---------------------------------------------------------------------------
#define GBM 128
#define GBN 128
#define GBK 16
#define APITCH 20     // conflict-free A frag reads (g*20+tg distinct banks)
#define BPITCH 136    // conflict-free B frag reads

__device__ __forceinline__ uint32_t f2tf32(float x) {
    uint32_t u;
    asm("cvt.rna.tf32.f32 %0, %1;" : "=r"(u) : "f"(x));
    return u;
}

#define MMA_TF32(d, a, b)                                                     \
    asm volatile(                                                             \
        "mma.sync.aligned.m16n8k8.row.col.f32.tf32.tf32.f32 "                 \
        "{%0,%1,%2,%3}, {%4,%5,%6,%7}, {%8,%9}, {%0,%1,%2,%3};"               \
        : "+f"((d)[0]), "+f"((d)[1]), "+f"((d)[2]), "+f"((d)[3])              \
        : "r"((a)[0]), "r"((a)[1]), "r"((a)[2]), "r"((a)[3]),                 \
          "r"((b)[0]), "r"((b)[1]))

__global__ __launch_bounds__(256, 2) void gemm_tf32_bias(
    const float* __restrict__ A, const float* __restrict__ B,
    const float* __restrict__ bias, float* __restrict__ C,
    int M, int N, int K)
{
    __shared__ uint32_t As[2][GBM * APITCH];   // 2*128*20*4 = 20.5 KB
    __shared__ uint32_t Bs[2][GBK * BPITCH];   // 2*16*136*4 = 17.4 KB

    const int tid    = threadIdx.x;
    const int wid    = tid >> 5;
    const int lane   = tid & 31;
    const int g      = lane >> 2;
    const int tg     = lane & 3;
    const int warp_m = (wid >> 2) * 64;
    const int warp_n = (wid & 3) * 32;

    const int bm = blockIdx.y * GBM;
    const int bn = blockIdx.x * GBN;

    // loader coords: 2 A float4s + 2 B float4s per thread per tile
    int am[2], ak[2], bk[2], bn4[2];
    #pragma unroll
    for (int i = 0; i < 2; i++) {
        int f = tid + i * 256;
        am[i]  = f >> 2;          // 0..127
        ak[i]  = (f & 3) * 4;     // 0,4,8,12
        bk[i]  = f >> 5;          // 0..15
        bn4[i] = (f & 31) * 4;
    }

    float acc[4][4][4];
    #pragma unroll
    for (int i = 0; i < 4; i++)
        #pragma unroll
        for (int j = 0; j < 4; j++)
            #pragma unroll
            for (int r = 0; r < 4; r++) acc[i][j][r] = 0.f;

    float4 rA[2], rB[2];

    #define LOADT(K0)                                                         \
        _Pragma("unroll")                                                     \
        for (int i = 0; i < 2; i++) {                                         \
            int gm = bm + am[i];                                              \
            rA[i] = (gm < M)                                                  \
                ? *(const float4*)(A + (size_t)gm * K + (K0) + ak[i])         \
                : make_float4(0.f, 0.f, 0.f, 0.f);                            \
            rB[i] = *(const float4*)(B + (size_t)((K0) + bk[i]) * N + bn + bn4[i]); \
        }

    #define STORET(BUF)                                                       \
        _Pragma("unroll")                                                     \
        for (int i = 0; i < 2; i++) {                                         \
            uint4 ua = make_uint4(f2tf32(rA[i].x), f2tf32(rA[i].y),           \
                                  f2tf32(rA[i].z), f2tf32(rA[i].w));          \
            *(uint4*)&As[BUF][am[i] * APITCH + ak[i]] = ua;                   \
            uint4 ub = make_uint4(f2tf32(rB[i].x), f2tf32(rB[i].y),           \
                                  f2tf32(rB[i].z), f2tf32(rB[i].w));          \
            *(uint4*)&Bs[BUF][bk[i] * BPITCH + bn4[i]] = ub;                  \
        }

    LOADT(0);
    STORET(0);
    __syncthreads();

    const int NT = K / GBK;
    for (int t = 0; t < NT; t++) {
        if (t + 1 < NT) { LOADT((t + 1) * GBK); }

        const uint32_t* as = As[t & 1];
        const uint32_t* bs = Bs[t & 1];
        #pragma unroll
        for (int ks = 0; ks < 2; ks++) {
            const int k8 = ks * 8;
            uint32_t afr[4][4], bfr[4][2];
            #pragma unroll
            for (int mi = 0; mi < 4; mi++) {
                int rb = warp_m + mi * 16 + g;
                afr[mi][0] = as[(rb)     * APITCH + k8 + tg];
                afr[mi][1] = as[(rb + 8) * APITCH + k8 + tg];
                afr[mi][2] = as[(rb)     * APITCH + k8 + tg + 4];
                afr[mi][3] = as[(rb + 8) * APITCH + k8 + tg + 4];
            }
            #pragma unroll
            for (int ni = 0; ni < 4; ni++) {
                int col = warp_n + ni * 8 + g;
                bfr[ni][0] = bs[(k8 + tg)     * BPITCH + col];
                bfr[ni][1] = bs[(k8 + tg + 4) * BPITCH + col];
            }
            #pragma unroll
            for (int mi = 0; mi < 4; mi++)
                #pragma unroll
                for (int ni = 0; ni < 4; ni++)
                    MMA_TF32(acc[mi][ni], afr[mi], bfr[ni]);
        }

        if (t + 1 < NT) { STORET((t + 1) & 1); }
        __syncthreads();
    }

    #pragma unroll
    for (int ni = 0; ni < 4; ni++) {
        const int col = bn + warp_n + ni * 8 + tg * 2;
        const float b0 = bias[col], b1 = bias[col + 1];
        #pragma unroll
        for (int mi = 0; mi < 4; mi++) {
            int r0 = bm + warp_m + mi * 16 + g;
            if (r0 < M)
                *(float2*)(C + (size_t)r0 * N + col) =
                    make_float2(acc[mi][ni][0] + b0, acc[mi][ni][1] + b1);
            int r1 = r0 + 8;
            if (r1 < M)
                *(float2*)(C + (size_t)r1 * N + col) =
                    make_float2(acc[mi][ni][2] + b0, acc[mi][ni][3] + b1);
        }
    }
    #undef LOADT
    #undef STORET
}

// ---------------------------------------------------------------------------
// Sampling with dedup + compaction. 2 queries per block.
//  softmax: 256 thr = 2 x 128 (head, lvl*4+pt)
//  gen:     64 thr = 2 x (head, level); merges points sharing a base voxel,
//           drops OOB corners, writes compacted (w, idx) list + count
//  gather:  warp = head; warp-uniform dynamic loop over compacted list
// ---------------------------------------------------------------------------
__global__ __launch_bounds__(256) void sample_kernel(
    const float* __restrict__ value,    // [Lin, 256]
    const float* __restrict__ refpts,   // [Lq, 4, 3]
    const float* __restrict__ off,      // [Lq, 384]
    const float* __restrict__ attn,     // [Lq, 128] logits
    float* __restrict__ sampled)        // [Lq, 256]
{
    const int q0  = blockIdx.x * 2;
    const int tid = threadIdx.x;

    __shared__ float  s_wp [2][128];
    __shared__ float2 s_cwi[2][8 * 128];   // [qi][h*128 + l*32 + slot]
    __shared__ int    s_cnt[2][32];        // [qi][h*4 + l]

    // ---- softmax ----
    {
        const int qi = tid >> 7;
        const int t  = tid & 127;
        float logit = attn[(size_t)(q0 + qi) * 128 + t];
        float mx = logit;
        #pragma unroll
        for (int m = 8; m; m >>= 1)
            mx = fmaxf(mx, __shfl_xor_sync(0xffffffffu, mx, m));
        float e = __expf(logit - mx);
        float sum = e;
        #pragma unroll
        for (int m = 8; m; m >>= 1)
            sum += __shfl_xor_sync(0xffffffffu, sum, m);
        s_wp[qi][t] = e / sum;
    }
    __syncthreads();

    // ---- corner gen + dedup + compaction ----
    if (tid < 64) {
        const int qi = tid >> 5;
        const int hl = tid & 31;
        const int h  = hl >> 2;
        const int l  = hl & 3;
        const int q  = q0 + qi;

        const int   S     = 32 >> l;
        const int   start = (l == 0) ? 0 : (l == 1) ? 32768
                          : (l == 2) ? 36864 : 37376;
        const float fS    = (float)S;

        const float rx = refpts[(size_t)q * 12 + l * 3 + 0];
        const float ry = refpts[(size_t)q * 12 + l * 3 + 1];
        const float rz = refpts[(size_t)q * 12 + l * 3 + 2];

        const float* ob = off + (size_t)q * 384 + h * 48 + l * 12;
        float po[12];
        *(float4*)&po[0] = *(const float4*)(ob);
        *(float4*)&po[4] = *(const float4*)(ob + 4);
        *(float4*)&po[8] = *(const float4*)(ob + 8);

        int   bx[4], by[4], bz[4];
        float w[4][8];
        #pragma unroll
        for (int j = 0; j < 4; j++)
            #pragma unroll
            for (int c = 0; c < 8; c++) w[j][c] = 0.f;
        int nslots = 0;

        #pragma unroll
        for (int p = 0; p < 4; p++) {
            const float wp = s_wp[qi][h * 16 + l * 4 + p];
            const float ix = fmaf(rx, fS, po[p * 3 + 0] - 0.5f);
            const float iy = fmaf(ry, fS, po[p * 3 + 1] - 0.5f);
            const float iz = fmaf(rz, fS, po[p * 3 + 2] - 0.5f);
            const float xf = floorf(ix), yf = floorf(iy), zf = floorf(iz);
            const float fx = ix - xf, fy = iy - yf, fz = iz - zf;
            const int x0 = (int)xf, y0 = (int)yf, z0 = (int)zf;

            bool m[4];
            #pragma unroll
            for (int j = 0; j < 4; j++)
                m[j] = (j < nslots) & (x0 == bx[j]) & (y0 == by[j]) & (z0 == bz[j]);
            const bool hit = m[0] | m[1] | m[2] | m[3];
            #pragma unroll
            for (int j = 0; j < 4; j++)
                if (!hit && j == nslots) {
                    bx[j] = x0; by[j] = y0; bz[j] = z0; m[j] = true;
                }
            if (!hit) nslots++;

            const float wx1 = fx, wx0 = 1.f - fx;
            const float wy1 = fy, wy0 = 1.f - fy;
            const float wz1 = fz, wz0 = 1.f - fz;
            #pragma unroll
            for (int c = 0; c < 8; c++) {
                float cw = wp * ((c & 1) ? wx1 : wx0)
                              * (((c >> 1) & 1) ? wy1 : wy0)
                              * ((c >> 2) ? wz1 : wz0);
                #pragma unroll
                for (int j = 0; j < 4; j++)
                    if (m[j]) w[j][c] += cw;
            }
        }

        // emit compacted, rotated to spread banks
        float2* dst = &s_cwi[qi][h * 128 + l * 32];
        const int rot = hl;
        int k = 0;
        #pragma unroll
        for (int j = 0; j < 4; j++) {
            if (j < nslots) {
                #pragma unroll
                for (int c = 0; c < 8; c++) {
                    const int xc = bx[j] + (c & 1);
                    const int yc = by[j] + ((c >> 1) & 1);
                    const int zc = bz[j] + (c >> 2);
                    if (((unsigned)xc < (unsigned)S) &
                        ((unsigned)yc < (unsigned)S) &
                        ((unsigned)zc < (unsigned)S)) {
                        const int idx = (start + (zc * S + yc) * S + xc) * DM;
                        dst[(k + rot) & 31] =
                            make_float2(w[j][c], __int_as_float(idx));
                        k++;
                    }
                }
            }
        }
        s_cnt[qi][hl] = k;
    }
    __syncthreads();

    // ---- gather ----
    const int h    = tid >> 5;
    const int lane = tid & 31;
    const float* vbase = value + h * CHEAD + lane;

    #pragma unroll
    for (int qi = 0; qi < 2; qi++) {
        float a0 = 0.f, a1 = 0.f;
        #pragma unroll
        for (int l = 0; l < 4; l++) {
            const int n   = s_cnt[qi][h * 4 + l];
            const int rot = h * 4 + l;
            const float2* p = &s_cwi[qi][h * 128 + l * 32];
            int j = 0;
            for (; j + 1 < n; j += 2) {
                float2 e0 = p[(j + rot) & 31];
                float2 e1 = p[(j + 1 + rot) & 31];
                a0 = fmaf(e0.x, __ldg(vbase + __float_as_int(e0.y)), a0);
                a1 = fmaf(e1.x, __ldg(vbase + __float_as_int(e1.y)), a1);
            }
            if (j < n) {
                float2 e = p[(j + rot) & 31];
                a0 = fmaf(e.x, __ldg(vbase + __float_as_int(e.y)), a0);
            }
        }
        sampled[(size_t)(q0 + qi) * DM + h * CHEAD + lane] = a0 + a1;
    }
}

// ---------------------------------------------------------------------------
extern "C" void kernel_launch(void* const* d_in, const int* in_sizes, int n_in,
                              void* d_out, int out_size)
{
    const float* query   = (const float*)d_in[0];
    const float* refpts  = (const float*)d_in[1];
    const float* inflat  = (const float*)d_in[2];
    const float* W_value = (const float*)d_in[5];
    const float* b_value = (const float*)d_in[6];
    const float* W_off   = (const float*)d_in[7];
    const float* b_off   = (const float*)d_in[8];
    const float* W_attn  = (const float*)d_in[9];
    const float* b_attn  = (const float*)d_in[10];
    const float* W_out   = (const float*)d_in[11];
    const float* b_out   = (const float*)d_in[12];
    float* out = (float*)d_out;

    float *p_value, *p_off, *p_attn, *p_sampled;
    cudaGetSymbolAddress((void**)&p_value,   g_value);
    cudaGetSymbolAddress((void**)&p_off,     g_off);
    cudaGetSymbolAddress((void**)&p_attn,    g_attn);
    cudaGetSymbolAddress((void**)&p_sampled, g_sampled);

    dim3 block(256);
    const int mb = (LQ + GBM - 1) / GBM;   // 293

    gemm_tf32_bias<<<dim3(DM / GBN, mb), block>>>(inflat, W_value, b_value, p_value, LIN, DM, DM);
    gemm_tf32_bias<<<dim3(384 / GBN, mb), block>>>(query, W_off, b_off, p_off, LQ, 384, DM);
    gemm_tf32_bias<<<dim3(128 / GBN, mb), block>>>(query, W_attn, b_attn, p_attn, LQ, 128, DM);
    sample_kernel<<<LQ / 2, block>>>(p_value, refpts, p_off, p_attn, p_sampled);
    gemm_tf32_bias<<<dim3(DM / GBN, mb), block>>>(p_sampled, W_out, b_out, out, LQ, DM, DM);
}

// round 5
// speedup vs baseline: 1.2805x; 1.2805x over previous
#include <cuda_runtime.h>
#include <math.h>
#include <stdint.h>

#define LQ      37440
#define LIN     37440
#define DM      256
#define NHEADS  8
#define CHEAD   32

// scratch (allocation-free per harness rules)
__device__ float g_value  [LIN * DM];
__device__ float g_off    [LQ * 384];
__device__ float g_attn   [LQ * 128];
__device__ float g_sampled[LQ * DM];

// ---------------------------------------------------------------------------
// tf32 tensor-core GEMM: C[M,N] = A[M,K] @ B[K,N] + bias[N]   (R3 version)
// BM=128, BN=128, BK=32, 256 threads (8 warps, 2x4), warp tile 64x32,
// mma.sync.m16n8k8.tf32. N % 128 == 0, K % 32 == 0. M bounds-checked.
// ---------------------------------------------------------------------------
#define GBM 128
#define GBN 128
#define GBK 32
#define APITCH 36
#define BPITCH 136

__device__ __forceinline__ uint32_t f2tf32(float x) {
    uint32_t u;
    asm("cvt.rna.tf32.f32 %0, %1;" : "=r"(u) : "f"(x));
    return u;
}

#define MMA_TF32(d, a, b)                                                     \
    asm volatile(                                                             \
        "mma.sync.aligned.m16n8k8.row.col.f32.tf32.tf32.f32 "                 \
        "{%0,%1,%2,%3}, {%4,%5,%6,%7}, {%8,%9}, {%0,%1,%2,%3};"               \
        : "+f"((d)[0]), "+f"((d)[1]), "+f"((d)[2]), "+f"((d)[3])              \
        : "r"((a)[0]), "r"((a)[1]), "r"((a)[2]), "r"((a)[3]),                 \
          "r"((b)[0]), "r"((b)[1]))

__global__ __launch_bounds__(256, 2) void gemm_tf32_bias(
    const float* __restrict__ A, const float* __restrict__ B,
    const float* __restrict__ bias, float* __restrict__ C,
    int M, int N, int K)
{
    __shared__ uint32_t As[GBM * APITCH];
    __shared__ uint32_t Bs[GBK * BPITCH];

    const int tid    = threadIdx.x;
    const int wid    = tid >> 5;
    const int lane   = tid & 31;
    const int g      = lane >> 2;
    const int tg     = lane & 3;
    const int warp_m = (wid >> 2) * 64;
    const int warp_n = (wid & 3) * 32;

    const int bm = blockIdx.y * GBM;
    const int bn = blockIdx.x * GBN;

    float acc[4][4][4];
    #pragma unroll
    for (int i = 0; i < 4; i++)
        #pragma unroll
        for (int j = 0; j < 4; j++)
            #pragma unroll
            for (int r = 0; r < 4; r++) acc[i][j][r] = 0.f;

    for (int k0 = 0; k0 < K; k0 += GBK) {
        #pragma unroll
        for (int it = 0; it < 4; it++) {
            int f  = tid + it * 256;
            int m  = f >> 3;
            int k4 = (f & 7) * 4;
            int gm = bm + m;
            float4 a = make_float4(0.f, 0.f, 0.f, 0.f);
            if (gm < M)
                a = *(const float4*)(A + (size_t)gm * K + k0 + k4);
            uint32_t* dst = &As[m * APITCH + k4];
            dst[0] = f2tf32(a.x); dst[1] = f2tf32(a.y);
            dst[2] = f2tf32(a.z); dst[3] = f2tf32(a.w);
        }
        #pragma unroll
        for (int it = 0; it < 4; it++) {
            int f  = tid + it * 256;
            int kk = f >> 5;
            int n4 = (f & 31) * 4;
            float4 b = *(const float4*)(B + (size_t)(k0 + kk) * N + bn + n4);
            uint32_t* dst = &Bs[kk * BPITCH + n4];
            dst[0] = f2tf32(b.x); dst[1] = f2tf32(b.y);
            dst[2] = f2tf32(b.z); dst[3] = f2tf32(b.w);
        }
        __syncthreads();

        #pragma unroll
        for (int ks = 0; ks < 4; ks++) {
            const int k8 = ks * 8;
            uint32_t afr[4][4], bfr[4][2];
            #pragma unroll
            for (int mi = 0; mi < 4; mi++) {
                int rb = warp_m + mi * 16 + g;
                afr[mi][0] = As[(rb)     * APITCH + k8 + tg];
                afr[mi][1] = As[(rb + 8) * APITCH + k8 + tg];
                afr[mi][2] = As[(rb)     * APITCH + k8 + tg + 4];
                afr[mi][3] = As[(rb + 8) * APITCH + k8 + tg + 4];
            }
            #pragma unroll
            for (int ni = 0; ni < 4; ni++) {
                int col = warp_n + ni * 8 + g;
                bfr[ni][0] = Bs[(k8 + tg)     * BPITCH + col];
                bfr[ni][1] = Bs[(k8 + tg + 4) * BPITCH + col];
            }
            #pragma unroll
            for (int mi = 0; mi < 4; mi++)
                #pragma unroll
                for (int ni = 0; ni < 4; ni++)
                    MMA_TF32(acc[mi][ni], afr[mi], bfr[ni]);
        }
        __syncthreads();
    }

    #pragma unroll
    for (int ni = 0; ni < 4; ni++) {
        const int col = bn + warp_n + ni * 8 + tg * 2;
        const float b0 = bias[col], b1 = bias[col + 1];
        #pragma unroll
        for (int mi = 0; mi < 4; mi++) {
            int r0 = bm + warp_m + mi * 16 + g;
            if (r0 < M)
                *(float2*)(C + (size_t)r0 * N + col) =
                    make_float2(acc[mi][ni][0] + b0, acc[mi][ni][1] + b1);
            int r1 = r0 + 8;
            if (r1 < M)
                *(float2*)(C + (size_t)r1 * N + col) =
                    make_float2(acc[mi][ni][2] + b0, acc[mi][ni][3] + b1);
        }
    }
}

// ---------------------------------------------------------------------------
// Sampling: 2 queries per block, vectorized gather.
//  phase 1: 256 thr = 2 x 128 (head,point) pairs -> softmax + 8 corners each
//  phase 2: warp = head; 4 lane-groups of 8 each load one corner's 32
//           channels as LDG.128 (predicated on w!=0), then xor-shuffle reduce
// ---------------------------------------------------------------------------
__global__ __launch_bounds__(256) void sample_kernel(
    const float* __restrict__ value,    // [Lin, 256]
    const float* __restrict__ refpts,   // [Lq, 4, 3]
    const float* __restrict__ off,      // [Lq, 384]
    const float* __restrict__ attn,     // [Lq, 128] logits
    float* __restrict__ sampled)        // [Lq, 256]
{
    const int q0  = blockIdx.x * 2;
    const int tid = threadIdx.x;

    __shared__ float2 s_cwi[2][128 * 8];   // (weight, idx*256 bitcast), 16KB

    {
        const int qi = tid >> 7;
        const int t  = tid & 127;
        const int q  = q0 + qi;
        const int h  = t >> 4;
        const int p  = t & 15;
        const int l  = p >> 2;
        const int pt = p & 3;

        // softmax over the 16-lane group
        float logit = attn[(size_t)q * 128 + t];
        float mx = logit;
        #pragma unroll
        for (int m = 8; m; m >>= 1)
            mx = fmaxf(mx, __shfl_xor_sync(0xffffffffu, mx, m));
        float e = __expf(logit - mx);
        float sum = e;
        #pragma unroll
        for (int m = 8; m; m >>= 1)
            sum += __shfl_xor_sync(0xffffffffu, sum, m);
        const float wp = e / sum;

        const int   S     = 32 >> l;
        const int   start = (l == 0) ? 0 : (l == 1) ? 32768
                          : (l == 2) ? 36864 : 37376;
        const float fS    = (float)S;

        const float rx = refpts[(size_t)q * 12 + l * 3 + 0];
        const float ry = refpts[(size_t)q * 12 + l * 3 + 1];
        const float rz = refpts[(size_t)q * 12 + l * 3 + 2];

        const size_t ob = (size_t)q * 384 + h * 48 + l * 12 + pt * 3;
        const float ix = fmaf(rx, fS, off[ob + 0] - 0.5f);
        const float iy = fmaf(ry, fS, off[ob + 1] - 0.5f);
        const float iz = fmaf(rz, fS, off[ob + 2] - 0.5f);

        const float x0f = floorf(ix), y0f = floorf(iy), z0f = floorf(iz);
        const float fx = ix - x0f, fy = iy - y0f, fz = iz - z0f;
        const int x0 = (int)x0f, y0 = (int)y0f, z0 = (int)z0f;

        const float wxv[2] = {1.f - fx, fx};
        const float wyv[2] = {1.f - fy, fy};
        const float wzv[2] = {1.f - fz, fz};

        #pragma unroll
        for (int dz = 0; dz < 2; dz++) {
            const int zc = z0 + dz;
            #pragma unroll
            for (int dy = 0; dy < 2; dy++) {
                const int yc = y0 + dy;
                #pragma unroll
                for (int dx = 0; dx < 2; dx++) {
                    const int xc = x0 + dx;
                    const int c  = dz * 4 + dy * 2 + dx;
                    const bool valid = ((unsigned)xc < (unsigned)S) &
                                       ((unsigned)yc < (unsigned)S) &
                                       ((unsigned)zc < (unsigned)S);
                    float w  = valid ? wp * wzv[dz] * wyv[dy] * wxv[dx] : 0.f;
                    int  idx = valid ? (start + (zc * S + yc) * S + xc) * DM : 0;
                    s_cwi[qi][t * 8 + c] = make_float2(w, __int_as_float(idx));
                }
            }
        }
    }
    __syncthreads();

    const int h    = tid >> 5;
    const int lane = tid & 31;
    const int grp  = lane >> 3;    // corner group 0..3
    const int cg   = lane & 7;     // channel quad: floats [cg*4, cg*4+4)
    const float* vbase = value + h * CHEAD + cg * 4;

    #pragma unroll
    for (int qi = 0; qi < 2; qi++) {
        const float2* cw = s_cwi[qi] + h * 128 + grp;
        float ax = 0.f, ay = 0.f, az = 0.f, aw = 0.f;

        #pragma unroll 4
        for (int j = 0; j < 32; j++) {
            float2 e = cw[j * 4];
            if (e.x != 0.f) {
                const float4 v =
                    *(const float4*)(vbase + __float_as_int(e.y));
                ax = fmaf(e.x, v.x, ax);
                ay = fmaf(e.x, v.y, ay);
                az = fmaf(e.x, v.z, az);
                aw = fmaf(e.x, v.w, aw);
            }
        }

        // reduce across the 4 corner groups (lanes xor 8, xor 16)
        #pragma unroll
        for (int m = 8; m <= 16; m <<= 1) {
            ax += __shfl_xor_sync(0xffffffffu, ax, m);
            ay += __shfl_xor_sync(0xffffffffu, ay, m);
            az += __shfl_xor_sync(0xffffffffu, az, m);
            aw += __shfl_xor_sync(0xffffffffu, aw, m);
        }
        if (lane < 8)
            *(float4*)(sampled + (size_t)(q0 + qi) * DM + h * CHEAD + cg * 4)
                = make_float4(ax, ay, az, aw);
    }
}

// ---------------------------------------------------------------------------
extern "C" void kernel_launch(void* const* d_in, const int* in_sizes, int n_in,
                              void* d_out, int out_size)
{
    const float* query   = (const float*)d_in[0];
    const float* refpts  = (const float*)d_in[1];
    const float* inflat  = (const float*)d_in[2];
    const float* W_value = (const float*)d_in[5];
    const float* b_value = (const float*)d_in[6];
    const float* W_off   = (const float*)d_in[7];
    const float* b_off   = (const float*)d_in[8];
    const float* W_attn  = (const float*)d_in[9];
    const float* b_attn  = (const float*)d_in[10];
    const float* W_out   = (const float*)d_in[11];
    const float* b_out   = (const float*)d_in[12];
    float* out = (float*)d_out;

    float *p_value, *p_off, *p_attn, *p_sampled;
    cudaGetSymbolAddress((void**)&p_value,   g_value);
    cudaGetSymbolAddress((void**)&p_off,     g_off);
    cudaGetSymbolAddress((void**)&p_attn,    g_attn);
    cudaGetSymbolAddress((void**)&p_sampled, g_sampled);

    dim3 block(256);
    const int mb = (LQ + GBM - 1) / GBM;   // 293

    gemm_tf32_bias<<<dim3(DM / GBN, mb), block>>>(inflat, W_value, b_value, p_value, LIN, DM, DM);
    gemm_tf32_bias<<<dim3(384 / GBN, mb), block>>>(query, W_off, b_off, p_off, LQ, 384, DM);
    gemm_tf32_bias<<<dim3(128 / GBN, mb), block>>>(query, W_attn, b_attn, p_attn, LQ, 128, DM);
    sample_kernel<<<LQ / 2, block>>>(p_value, refpts, p_off, p_attn, p_sampled);
    gemm_tf32_bias<<<dim3(DM / GBN, mb), block>>>(p_sampled, W_out, b_out, out, LQ, DM, DM);
}

// round 6
// speedup vs baseline: 1.3972x; 1.0911x over previous
#include <cuda_runtime.h>
#include <math.h>
#include <stdint.h>

#define LQ      37440
#define LIN     37440
#define DM      256
#define NHEADS  8
#define CHEAD   32

// scratch (allocation-free per harness rules)
__device__ float g_value  [LIN * DM];
__device__ float g_off    [LQ * 384];
__device__ float g_attn   [LQ * 128];
__device__ float g_sampled[LQ * DM];

// ---------------------------------------------------------------------------
// tf32 tensor-core GEMM: C[M,N] = A[M,K] @ B[K,N] + bias[N]
// BM=128, BN=128, BK=32, 256 threads (8 warps, 2x4), warp tile 64x32,
// mma.sync.m16n8k8.tf32. N % 128 == 0, K % 32 == 0. M bounds-checked.
// ---------------------------------------------------------------------------
#define GBM 128
#define GBN 128
#define GBK 32
#define APITCH 36
#define BPITCH 136

__device__ __forceinline__ uint32_t f2tf32(float x) {
    uint32_t u;
    asm("cvt.rna.tf32.f32 %0, %1;" : "=r"(u) : "f"(x));
    return u;
}

#define MMA_TF32(d, a, b)                                                     \
    asm volatile(                                                             \
        "mma.sync.aligned.m16n8k8.row.col.f32.tf32.tf32.f32 "                 \
        "{%0,%1,%2,%3}, {%4,%5,%6,%7}, {%8,%9}, {%0,%1,%2,%3};"               \
        : "+f"((d)[0]), "+f"((d)[1]), "+f"((d)[2]), "+f"((d)[3])              \
        : "r"((a)[0]), "r"((a)[1]), "r"((a)[2]), "r"((a)[3]),                 \
          "r"((b)[0]), "r"((b)[1]))

__global__ __launch_bounds__(256, 2) void gemm_tf32_bias(
    const float* __restrict__ A, const float* __restrict__ B,
    const float* __restrict__ bias, float* __restrict__ C,
    int M, int N, int K)
{
    __shared__ uint32_t As[GBM * APITCH];
    __shared__ uint32_t Bs[GBK * BPITCH];

    const int tid    = threadIdx.x;
    const int wid    = tid >> 5;
    const int lane   = tid & 31;
    const int g      = lane >> 2;
    const int tg     = lane & 3;
    const int warp_m = (wid >> 2) * 64;
    const int warp_n = (wid & 3) * 32;

    const int bm = blockIdx.y * GBM;
    const int bn = blockIdx.x * GBN;

    float acc[4][4][4];
    #pragma unroll
    for (int i = 0; i < 4; i++)
        #pragma unroll
        for (int j = 0; j < 4; j++)
            #pragma unroll
            for (int r = 0; r < 4; r++) acc[i][j][r] = 0.f;

    for (int k0 = 0; k0 < K; k0 += GBK) {
        #pragma unroll
        for (int it = 0; it < 4; it++) {
            int f  = tid + it * 256;
            int m  = f >> 3;
            int k4 = (f & 7) * 4;
            int gm = bm + m;
            float4 a = make_float4(0.f, 0.f, 0.f, 0.f);
            if (gm < M)
                a = *(const float4*)(A + (size_t)gm * K + k0 + k4);
            uint32_t* dst = &As[m * APITCH + k4];
            dst[0] = f2tf32(a.x); dst[1] = f2tf32(a.y);
            dst[2] = f2tf32(a.z); dst[3] = f2tf32(a.w);
        }
        #pragma unroll
        for (int it = 0; it < 4; it++) {
            int f  = tid + it * 256;
            int kk = f >> 5;
            int n4 = (f & 31) * 4;
            float4 b = *(const float4*)(B + (size_t)(k0 + kk) * N + bn + n4);
            uint32_t* dst = &Bs[kk * BPITCH + n4];
            dst[0] = f2tf32(b.x); dst[1] = f2tf32(b.y);
            dst[2] = f2tf32(b.z); dst[3] = f2tf32(b.w);
        }
        __syncthreads();

        #pragma unroll
        for (int ks = 0; ks < 4; ks++) {
            const int k8 = ks * 8;
            uint32_t afr[4][4], bfr[4][2];
            #pragma unroll
            for (int mi = 0; mi < 4; mi++) {
                int rb = warp_m + mi * 16 + g;
                afr[mi][0] = As[(rb)     * APITCH + k8 + tg];
                afr[mi][1] = As[(rb + 8) * APITCH + k8 + tg];
                afr[mi][2] = As[(rb)     * APITCH + k8 + tg + 4];
                afr[mi][3] = As[(rb + 8) * APITCH + k8 + tg + 4];
            }
            #pragma unroll
            for (int ni = 0; ni < 4; ni++) {
                int col = warp_n + ni * 8 + g;
                bfr[ni][0] = Bs[(k8 + tg)     * BPITCH + col];
                bfr[ni][1] = Bs[(k8 + tg + 4) * BPITCH + col];
            }
            #pragma unroll
            for (int mi = 0; mi < 4; mi++)
                #pragma unroll
                for (int ni = 0; ni < 4; ni++)
                    MMA_TF32(acc[mi][ni], afr[mi], bfr[ni]);
        }
        __syncthreads();
    }

    #pragma unroll
    for (int ni = 0; ni < 4; ni++) {
        const int col = bn + warp_n + ni * 8 + tg * 2;
        const float b0 = bias[col], b1 = bias[col + 1];
        #pragma unroll
        for (int mi = 0; mi < 4; mi++) {
            int r0 = bm + warp_m + mi * 16 + g;
            if (r0 < M)
                *(float2*)(C + (size_t)r0 * N + col) =
                    make_float2(acc[mi][ni][0] + b0, acc[mi][ni][1] + b1);
            int r1 = r0 + 8;
            if (r1 < M)
                *(float2*)(C + (size_t)r1 * N + col) =
                    make_float2(acc[mi][ni][2] + b0, acc[mi][ni][3] + b1);
        }
    }
}

// ---------------------------------------------------------------------------
// Sampling: 2 queries per block, vectorized gather.
//  phase 1: 256 thr = 2 x 128 (head,point) pairs -> softmax + 8 corners each,
//           stored CORNER-MAJOR [h][c*16 + p] so STS is bank-conflict-free
//  phase 2: warp = head; 4 lane-groups of 8 each load one corner's 32
//           channels as LDG.128 (predicated on w!=0), then xor-shuffle reduce
// ---------------------------------------------------------------------------
__global__ __launch_bounds__(256) void sample_kernel(
    const float* __restrict__ value,    // [Lin, 256]
    const float* __restrict__ refpts,   // [Lq, 4, 3]
    const float* __restrict__ off,      // [Lq, 384]
    const float* __restrict__ attn,     // [Lq, 128] logits
    float* __restrict__ sampled)        // [Lq, 256]
{
    const int q0  = blockIdx.x * 2;
    const int tid = threadIdx.x;

    __shared__ float2 s_cwi[2][128 * 8];   // [qi][h*128 + c*16 + p], 16KB

    {
        const int qi = tid >> 7;
        const int t  = tid & 127;
        const int q  = q0 + qi;
        const int h  = t >> 4;
        const int p  = t & 15;
        const int l  = p >> 2;
        const int pt = p & 3;

        // softmax over the 16-lane group
        float logit = attn[(size_t)q * 128 + t];
        float mx = logit;
        #pragma unroll
        for (int m = 8; m; m >>= 1)
            mx = fmaxf(mx, __shfl_xor_sync(0xffffffffu, mx, m));
        float e = __expf(logit - mx);
        float sum = e;
        #pragma unroll
        for (int m = 8; m; m >>= 1)
            sum += __shfl_xor_sync(0xffffffffu, sum, m);
        const float wp = e / sum;

        const int   S     = 32 >> l;
        const int   start = (l == 0) ? 0 : (l == 1) ? 32768
                          : (l == 2) ? 36864 : 37376;
        const float fS    = (float)S;

        const float rx = refpts[(size_t)q * 12 + l * 3 + 0];
        const float ry = refpts[(size_t)q * 12 + l * 3 + 1];
        const float rz = refpts[(size_t)q * 12 + l * 3 + 2];

        const size_t ob = (size_t)q * 384 + h * 48 + l * 12 + pt * 3;
        const float ix = fmaf(rx, fS, off[ob + 0] - 0.5f);
        const float iy = fmaf(ry, fS, off[ob + 1] - 0.5f);
        const float iz = fmaf(rz, fS, off[ob + 2] - 0.5f);

        const float x0f = floorf(ix), y0f = floorf(iy), z0f = floorf(iz);
        const float fx = ix - x0f, fy = iy - y0f, fz = iz - z0f;
        const int x0 = (int)x0f, y0 = (int)y0f, z0 = (int)z0f;

        const float wxv[2] = {1.f - fx, fx};
        const float wyv[2] = {1.f - fy, fy};
        const float wzv[2] = {1.f - fz, fz};

        float2* dst = &s_cwi[qi][h * 128 + p];

        #pragma unroll
        for (int dz = 0; dz < 2; dz++) {
            const int zc = z0 + dz;
            #pragma unroll
            for (int dy = 0; dy < 2; dy++) {
                const int yc = y0 + dy;
                #pragma unroll
                for (int dx = 0; dx < 2; dx++) {
                    const int xc = x0 + dx;
                    const int c  = dz * 4 + dy * 2 + dx;
                    const bool valid = ((unsigned)xc < (unsigned)S) &
                                       ((unsigned)yc < (unsigned)S) &
                                       ((unsigned)zc < (unsigned)S);
                    float w  = valid ? wp * wzv[dz] * wyv[dy] * wxv[dx] : 0.f;
                    int  idx = valid ? (start + (zc * S + yc) * S + xc) * DM : 0;
                    dst[c * 16] = make_float2(w, __int_as_float(idx));
                }
            }
        }
    }
    __syncthreads();

    const int h    = tid >> 5;
    const int lane = tid & 31;
    const int grp  = lane >> 3;    // list-entry group 0..3
    const int cg   = lane & 7;     // channel quad: floats [cg*4, cg*4+4)
    const float* vbase = value + h * CHEAD + cg * 4;

    #pragma unroll
    for (int qi = 0; qi < 2; qi++) {
        const float2* cw = s_cwi[qi] + h * 128 + grp;
        float ax = 0.f, ay = 0.f, az = 0.f, aw = 0.f;

        #pragma unroll 4
        for (int j = 0; j < 32; j++) {
            float2 e = cw[j * 4];
            if (e.x != 0.f) {
                const float4 v =
                    *(const float4*)(vbase + __float_as_int(e.y));
                ax = fmaf(e.x, v.x, ax);
                ay = fmaf(e.x, v.y, ay);
                az = fmaf(e.x, v.z, az);
                aw = fmaf(e.x, v.w, aw);
            }
        }

        // reduce across the 4 groups (lanes xor 8, xor 16)
        #pragma unroll
        for (int m = 8; m <= 16; m <<= 1) {
            ax += __shfl_xor_sync(0xffffffffu, ax, m);
            ay += __shfl_xor_sync(0xffffffffu, ay, m);
            az += __shfl_xor_sync(0xffffffffu, az, m);
            aw += __shfl_xor_sync(0xffffffffu, aw, m);
        }
        if (lane < 8)
            *(float4*)(sampled + (size_t)(q0 + qi) * DM + h * CHEAD + cg * 4)
                = make_float4(ax, ay, az, aw);
    }
}

// ---------------------------------------------------------------------------
extern "C" void kernel_launch(void* const* d_in, const int* in_sizes, int n_in,
                              void* d_out, int out_size)
{
    const float* query   = (const float*)d_in[0];
    const float* refpts  = (const float*)d_in[1];
    const float* inflat  = (const float*)d_in[2];
    const float* W_value = (const float*)d_in[5];
    const float* b_value = (const float*)d_in[6];
    const float* W_off   = (const float*)d_in[7];
    const float* b_off   = (const float*)d_in[8];
    const float* W_attn  = (const float*)d_in[9];
    const float* b_attn  = (const float*)d_in[10];
    const float* W_out   = (const float*)d_in[11];
    const float* b_out   = (const float*)d_in[12];
    float* out = (float*)d_out;

    float *p_value, *p_off, *p_attn, *p_sampled;
    cudaGetSymbolAddress((void**)&p_value,   g_value);
    cudaGetSymbolAddress((void**)&p_off,     g_off);
    cudaGetSymbolAddress((void**)&p_attn,    g_attn);
    cudaGetSymbolAddress((void**)&p_sampled, g_sampled);

    dim3 block(256);
    const int mb = (LQ + GBM - 1) / GBM;   // 293

    gemm_tf32_bias<<<dim3(DM / GBN, mb), block>>>(inflat, W_value, b_value, p_value, LIN, DM, DM);
    gemm_tf32_bias<<<dim3(384 / GBN, mb), block>>>(query, W_off, b_off, p_off, LQ, 384, DM);
    gemm_tf32_bias<<<dim3(128 / GBN, mb), block>>>(query, W_attn, b_attn, p_attn, LQ, 128, DM);
    sample_kernel<<<LQ / 2, block>>>(p_value, refpts, p_off, p_attn, p_sampled);
    gemm_tf32_bias<<<dim3(DM / GBN, mb), block>>>(p_sampled, W_out, b_out, out, LQ, DM, DM);
}